// round 10
// baseline (speedup 1.0000x reference)
#include <cuda_runtime.h>

#define NN 100000
#define NE 1600000
#define EPSV 1e-16f
#define NEG 0.2f

// Scratch (static __device__ — allocation-free)
__device__ float    g_rec1[NN * 8];  // per node: {as1[4], x0,x1,x2,0}
__device__ float    g_ad1[NN * 4];   // ad1 per node (4 heads)
__device__ float    g_acc1[NN * 16]; // layer1 rank-3 accumulators (4 heads x {wx0,wx1,wx2,w})
__device__ float    g_h2[NN * 32];
__device__ float    g_as2[NN];
__device__ float    g_ad2[NN];
__device__ float    g_acc2[NN * 32]; // layer2 weighted-sum accumulator
__device__ float    g_den2[NN];      // layer2 softmax denominator
__device__ float    g_u[NN * 32];
__device__ float    g_v[NN * 32];
__device__ float    g_p[24];         // folded attn: p_src[4][3], p_dst[4][3]

__device__ __forceinline__ float lrelu(float x) { return x > 0.f ? x : NEG * x; }
__device__ __forceinline__ float eluf(float x)  { return x > 0.f ? x : (__expf(x) - 1.f); }

__device__ __forceinline__ void red4(float* p, float a, float b, float c, float d) {
    asm volatile("red.global.add.v4.f32 [%0], {%1,%2,%3,%4};"
                 :: "l"(p), "f"(a), "f"(b), "f"(c), "f"(d) : "memory");
}
__device__ __forceinline__ void red1(float* p, float v) {
    asm volatile("red.global.add.f32 [%0], %1;" :: "l"(p), "f"(v) : "memory");
}

// ---------------------------------------------------------------- zero accumulators + fold attn vectors into W1 (block 0)
__global__ void k_zero(const float* __restrict__ w1, const float* __restrict__ as_,
                       const float* __restrict__ ad_) {
    int i = blockIdx.x * blockDim.x + threadIdx.x;
    int st = gridDim.x * blockDim.x;
    for (int j = i; j < NN * 16; j += st) g_acc1[j] = 0.f;
    for (int j = i; j < NN * 32; j += st) g_acc2[j] = 0.f;
    for (int j = i; j < NN;      j += st) g_den2[j] = 0.f;
    if (blockIdx.x == 0 && threadIdx.x < 24) {
        int t = threadIdx.x;
        int sd = t / 12;               // 0 = src, 1 = dst
        int h  = (t % 12) / 3;
        int j  = t % 3;
        const float* a = sd ? ad_ : as_;
        float acc = 0.f;
        for (int c = 0; c < 32; c++)
            acc += a[h * 32 + c] * w1[(h * 32 + c) * 3 + j];
        g_p[sd * 12 + h * 3 + j] = acc;
    }
}

// ---------------------------------------------------------------- node1: thread per node
// packed record {as1, x}, plus ad1
__global__ void k_node1(const float* __restrict__ x) {
    __shared__ float sp[24];
    if (threadIdx.x < 24) sp[threadIdx.x] = g_p[threadIdx.x];
    __syncthreads();
    int n = blockIdx.x * blockDim.x + threadIdx.x;
    if (n >= NN) return;
    float x0 = __ldg(x + n * 3);
    float x1 = __ldg(x + n * 3 + 1);
    float x2 = __ldg(x + n * 3 + 2);
    float4 as, ad;
    as.x = x0 * sp[0]  + x1 * sp[1]  + x2 * sp[2];
    as.y = x0 * sp[3]  + x1 * sp[4]  + x2 * sp[5];
    as.z = x0 * sp[6]  + x1 * sp[7]  + x2 * sp[8];
    as.w = x0 * sp[9]  + x1 * sp[10] + x2 * sp[11];
    ad.x = x0 * sp[12] + x1 * sp[13] + x2 * sp[14];
    ad.y = x0 * sp[15] + x1 * sp[16] + x2 * sp[17];
    ad.z = x0 * sp[18] + x1 * sp[19] + x2 * sp[20];
    ad.w = x0 * sp[21] + x1 * sp[22] + x2 * sp[23];
    *(float4*)(g_rec1 + n * 8)     = as;
    *(float4*)(g_rec1 + n * 8 + 4) = make_float4(x0, x1, x2, 0.f);
    *(float4*)(g_ad1 + n * 4)      = ad;
}

// ---------------------------------------------------------------- layer1 edge accumulation (thread per edge)
__global__ void k_l1e(const int* __restrict__ src, const int* __restrict__ dst) {
    int i = blockIdx.x * blockDim.x + threadIdx.x;
    int st = gridDim.x * blockDim.x;
    for (int e = i; e < NE; e += st) {
        int s = src[e], d = dst[e];
        float4 as = *(const float4*)(g_rec1 + s * 8);
        float4 xx = *(const float4*)(g_rec1 + s * 8 + 4);
        float4 ad = *(const float4*)(g_ad1 + d * 4);
        float w0 = __expf(lrelu(as.x + ad.x));
        float w1 = __expf(lrelu(as.y + ad.y));
        float w2 = __expf(lrelu(as.z + ad.z));
        float w3 = __expf(lrelu(as.w + ad.w));
        float* p = g_acc1 + d * 16;
        red4(p,      w0 * xx.x, w0 * xx.y, w0 * xx.z, w0);
        red4(p + 4,  w1 * xx.x, w1 * xx.y, w1 * xx.z, w1);
        red4(p + 8,  w2 * xx.x, w2 * xx.y, w2 * xx.z, w2);
        red4(p + 12, w3 * xx.x, w3 * xx.y, w3 * xx.z, w3);
    }
}

// ---------------------------------------------------------------- layer1 node finalize (warp per node):
// reconstruct 128-dim out via W1, bias+elu, layer2 projection 128->32 (4 indep chains),
// attn2 dots
__global__ void k_l1n(const float* __restrict__ w1, const float* __restrict__ w2,
                      const float* __restrict__ b1,
                      const float* __restrict__ a2s, const float* __restrict__ a2d) {
    __shared__ float s_w1[128 * 3];
    __shared__ float s_w2t[128 * 32];
    int tid = threadIdx.x;
    for (int i = tid; i < 384; i += blockDim.x) s_w1[i] = w1[i];
    for (int i = tid; i < 4096; i += blockDim.x) {
        int c = i >> 7, k = i & 127;
        s_w2t[k * 32 + c] = w2[i];
    }
    __syncthreads();
    int lane = tid & 31;
    int warp = (blockIdx.x * blockDim.x + tid) >> 5;
    int nw = (gridDim.x * blockDim.x) >> 5;
    for (int n = warp; n < NN; n += nw) {
        float v[4];
#pragma unroll
        for (int j = 0; j < 4; j++) {
            float4 A = *(const float4*)(g_acc1 + n * 16 + j * 4);  // broadcast load
            int k = j * 32 + lane;
            float inv = 1.f / (A.w + EPSV);
            float val = (s_w1[k * 3] * A.x + s_w1[k * 3 + 1] * A.y + s_w1[k * 3 + 2] * A.z) * inv;
            v[j] = eluf(val + __ldg(b1 + k));
        }
        // projection 128->32 with 4 independent accumulator chains:
        // k = j*32 + sl is held by lane sl in v[j]
        float pa0 = 0.f, pa1 = 0.f, pa2 = 0.f, pa3 = 0.f;
#pragma unroll
        for (int sl = 0; sl < 32; sl++) {
            float v0 = __shfl_sync(0xffffffffu, v[0], sl);
            float v1 = __shfl_sync(0xffffffffu, v[1], sl);
            float v2 = __shfl_sync(0xffffffffu, v[2], sl);
            float v3 = __shfl_sync(0xffffffffu, v[3], sl);
            pa0 += s_w2t[(sl)       * 32 + lane] * v0;
            pa1 += s_w2t[(32 + sl)  * 32 + lane] * v1;
            pa2 += s_w2t[(64 + sl)  * 32 + lane] * v2;
            pa3 += s_w2t[(96 + sl)  * 32 + lane] * v3;
        }
        float pa = (pa0 + pa1) + (pa2 + pa3);
        g_h2[n * 32 + lane] = pa;
        float ts = pa * __ldg(a2s + lane);
        float td = pa * __ldg(a2d + lane);
#pragma unroll
        for (int o = 16; o > 0; o >>= 1) {
            ts += __shfl_xor_sync(0xffffffffu, ts, o);
            td += __shfl_xor_sync(0xffffffffu, td, o);
        }
        if (lane == 0) { g_as2[n] = ts; g_ad2[n] = td; }
    }
}

// ---------------------------------------------------------------- layer2 edge accumulation (8 lanes per edge)
__global__ void k_l2e(const int* __restrict__ src, const int* __restrict__ dst) {
    int tid = threadIdx.x;
    int lane = tid & 31;
    int sub = lane & 7;
    int warp = (blockIdx.x * blockDim.x + tid) >> 5;
    int nw = (gridDim.x * blockDim.x) >> 5;
    for (int base = warp * 4; base < NE; base += nw * 4) {
        int e = base + (lane >> 3);   // NE % 4 == 0 → always valid
        int s = src[e], d = dst[e];
        float w = __expf(lrelu(g_as2[s] + g_ad2[d]));
        float4 h = *(const float4*)(g_h2 + s * 32 + sub * 4);
        red4(g_acc2 + d * 32 + sub * 4, w * h.x, w * h.y, w * h.z, w * h.w);
        if (sub == 0) red1(g_den2 + d, w);
    }
}

// ---------------------------------------------------------------- layer2 node finalize (warp per node):
// o = acc/den + b2, then u = o@W1a^T, v = o@W1b^T + mb1 (4 indep chains)
__global__ void k_l2n(const float* __restrict__ b2, const float* __restrict__ mw1,
                      const float* __restrict__ mb1) {
    __shared__ float s_wa[32 * 32];
    __shared__ float s_wb[32 * 32];
    int tid = threadIdx.x;
    for (int i = tid; i < 1024; i += blockDim.x) {
        int r = i >> 5, k = i & 31;
        s_wa[k * 32 + r] = mw1[r * 64 + k];
        s_wb[k * 32 + r] = mw1[r * 64 + 32 + k];
    }
    __syncthreads();
    int lane = tid & 31;
    int warp = (blockIdx.x * blockDim.x + tid) >> 5;
    int nw = (gridDim.x * blockDim.x) >> 5;
    for (int n = warp; n < NN; n += nw) {
        float o = g_acc2[n * 32 + lane] / (g_den2[n] + EPSV) + __ldg(b2 + lane);
        float u0 = 0.f, u1 = 0.f, v0 = 0.f, v1 = 0.f;
#pragma unroll
        for (int k = 0; k < 32; k += 2) {
            float bc0 = __shfl_sync(0xffffffffu, o, k);
            float bc1 = __shfl_sync(0xffffffffu, o, k + 1);
            u0 += s_wa[k * 32 + lane] * bc0;
            u1 += s_wa[(k + 1) * 32 + lane] * bc1;
            v0 += s_wb[k * 32 + lane] * bc0;
            v1 += s_wb[(k + 1) * 32 + lane] * bc1;
        }
        g_u[n * 32 + lane] = u0 + u1;
        g_v[n * 32 + lane] = v0 + v1 + __ldg(mb1 + lane);
    }
}

// ---------------------------------------------------------------- edge MLP: 8 lanes per edge
__global__ void k_mlp(const float* __restrict__ mw2, const float* __restrict__ mb2,
                      float* __restrict__ out,
                      const int* __restrict__ src, const int* __restrict__ dst) {
    int tid = threadIdx.x;
    int lane = tid & 31;
    int sub = lane & 7;
    int warp = (blockIdx.x * blockDim.x + tid) >> 5;
    int nw = (gridDim.x * blockDim.x) >> 5;
    float4 w2v = *(const float4*)(mw2 + sub * 4);
    float fb = __ldg(mb2);
    for (int base = warp * 4; base < NE; base += nw * 4) {
        int e = base + (lane >> 3);
        int s = src[e], d = dst[e];
        float4 uu = *(const float4*)(g_u + s * 32 + sub * 4);
        float4 vv = *(const float4*)(g_v + d * 32 + sub * 4);
        float t = fmaxf(uu.x + vv.x, 0.f) * w2v.x
                + fmaxf(uu.y + vv.y, 0.f) * w2v.y
                + fmaxf(uu.z + vv.z, 0.f) * w2v.z
                + fmaxf(uu.w + vv.w, 0.f) * w2v.w;
        t += __shfl_xor_sync(0xffffffffu, t, 4);
        t += __shfl_xor_sync(0xffffffffu, t, 2);
        t += __shfl_xor_sync(0xffffffffu, t, 1);
        if (sub == 0) out[e] = fmaxf(t + fb, 0.f);
    }
}

extern "C" void kernel_launch(void* const* d_in, const int* in_sizes, int n_in,
                              void* d_out, int out_size) {
    const float* x   = (const float*)d_in[0];
    const int*   ei  = (const int*)d_in[1];
    const float* w1  = (const float*)d_in[2];
    const float* as1 = (const float*)d_in[3];
    const float* ad1 = (const float*)d_in[4];
    const float* b1  = (const float*)d_in[5];
    const float* w2  = (const float*)d_in[6];
    const float* as2 = (const float*)d_in[7];
    const float* ad2 = (const float*)d_in[8];
    const float* b2  = (const float*)d_in[9];
    const float* mw1 = (const float*)d_in[10];
    const float* mb1 = (const float*)d_in[11];
    const float* mw2 = (const float*)d_in[12];
    const float* mb2 = (const float*)d_in[13];
    const int* src = ei;
    const int* dst = ei + NE;
    float* out = (float*)d_out;

    k_zero <<<2048, 256>>>(w1, as1, ad1);
    k_node1<<<(NN + 255) / 256, 256>>>(x);
    k_l1e  <<<2048, 256>>>(src, dst);
    k_l1n  <<<1024, 256>>>(w1, w2, b1, as2, ad2);
    k_l2e  <<<2048, 256>>>(src, dst);
    k_l2n  <<<512, 256>>>(b2, mw1, mb1);
    k_mlp  <<<2048, 256>>>(mw2, mb2, out, src, dst);
}

// round 12
// speedup vs baseline: 1.3205x; 1.3205x over previous
#include <cuda_runtime.h>

#define NN 100000
#define NE 1600000
#define EPSV 1e-16f
#define NEG 0.2f

// Scratch (static __device__ — allocation-free)
__device__ float    g_rec1[NN * 8];  // per node: {as1[4], x0,x1,x2,0}
__device__ float    g_ad1[NN * 4];   // ad1 per node (4 heads)
__device__ float    g_acc1[NN * 16]; // layer1 rank-3 accumulators (4 heads x {wx0,wx1,wx2,w})
__device__ float    g_h2[NN * 32];
__device__ float    g_as2[NN];
__device__ float    g_ad2[NN];
__device__ float    g_acc2[NN * 32]; // layer2 weighted-sum accumulator
__device__ float    g_den2[NN];      // layer2 softmax denominator
__device__ float    g_u[NN * 32];
__device__ float    g_v[NN * 32];
__device__ float    g_p[24];         // folded attn: p_src[4][3], p_dst[4][3]

__device__ __forceinline__ float lrelu(float x) { return x > 0.f ? x : NEG * x; }
__device__ __forceinline__ float eluf(float x)  { return x > 0.f ? x : (__expf(x) - 1.f); }

__device__ __forceinline__ void red4(float* p, float a, float b, float c, float d) {
    asm volatile("red.global.add.v4.f32 [%0], {%1,%2,%3,%4};"
                 :: "l"(p), "f"(a), "f"(b), "f"(c), "f"(d) : "memory");
}
__device__ __forceinline__ void red1(float* p, float v) {
    asm volatile("red.global.add.f32 [%0], %1;" :: "l"(p), "f"(v) : "memory");
}

// ---------------------------------------------------------------- zero accumulators + fold attn vectors into W1 (block 0)
__global__ void k_zero(const float* __restrict__ w1, const float* __restrict__ as_,
                       const float* __restrict__ ad_) {
    int i = blockIdx.x * blockDim.x + threadIdx.x;
    int st = gridDim.x * blockDim.x;
    for (int j = i; j < NN * 16; j += st) g_acc1[j] = 0.f;
    for (int j = i; j < NN * 32; j += st) g_acc2[j] = 0.f;
    for (int j = i; j < NN;      j += st) g_den2[j] = 0.f;
    if (blockIdx.x == 0 && threadIdx.x < 24) {
        int t = threadIdx.x;
        int sd = t / 12;               // 0 = src, 1 = dst
        int h  = (t % 12) / 3;
        int j  = t % 3;
        const float* a = sd ? ad_ : as_;
        float acc = 0.f;
        for (int c = 0; c < 32; c++)
            acc += a[h * 32 + c] * w1[(h * 32 + c) * 3 + j];
        g_p[sd * 12 + h * 3 + j] = acc;
    }
}

// ---------------------------------------------------------------- node1: thread per node
__global__ void k_node1(const float* __restrict__ x) {
    __shared__ float sp[24];
    if (threadIdx.x < 24) sp[threadIdx.x] = g_p[threadIdx.x];
    __syncthreads();
    int n = blockIdx.x * blockDim.x + threadIdx.x;
    if (n >= NN) return;
    float x0 = __ldg(x + n * 3);
    float x1 = __ldg(x + n * 3 + 1);
    float x2 = __ldg(x + n * 3 + 2);
    float4 as, ad;
    as.x = x0 * sp[0]  + x1 * sp[1]  + x2 * sp[2];
    as.y = x0 * sp[3]  + x1 * sp[4]  + x2 * sp[5];
    as.z = x0 * sp[6]  + x1 * sp[7]  + x2 * sp[8];
    as.w = x0 * sp[9]  + x1 * sp[10] + x2 * sp[11];
    ad.x = x0 * sp[12] + x1 * sp[13] + x2 * sp[14];
    ad.y = x0 * sp[15] + x1 * sp[16] + x2 * sp[17];
    ad.z = x0 * sp[18] + x1 * sp[19] + x2 * sp[20];
    ad.w = x0 * sp[21] + x1 * sp[22] + x2 * sp[23];
    *(float4*)(g_rec1 + n * 8)     = as;
    *(float4*)(g_rec1 + n * 8 + 4) = make_float4(x0, x1, x2, 0.f);
    *(float4*)(g_ad1 + n * 4)      = ad;
}

// ---------------------------------------------------------------- layer1 edge accumulation (thread per edge)
__global__ void k_l1e(const int* __restrict__ src, const int* __restrict__ dst) {
    int i = blockIdx.x * blockDim.x + threadIdx.x;
    int st = gridDim.x * blockDim.x;
    for (int e = i; e < NE; e += st) {
        int s = src[e], d = dst[e];
        float4 as = *(const float4*)(g_rec1 + s * 8);
        float4 xx = *(const float4*)(g_rec1 + s * 8 + 4);
        float4 ad = *(const float4*)(g_ad1 + d * 4);
        float w0 = __expf(lrelu(as.x + ad.x));
        float w1 = __expf(lrelu(as.y + ad.y));
        float w2 = __expf(lrelu(as.z + ad.z));
        float w3 = __expf(lrelu(as.w + ad.w));
        float* p = g_acc1 + d * 16;
        red4(p,      w0 * xx.x, w0 * xx.y, w0 * xx.z, w0);
        red4(p + 4,  w1 * xx.x, w1 * xx.y, w1 * xx.z, w1);
        red4(p + 8,  w2 * xx.x, w2 * xx.y, w2 * xx.z, w2);
        red4(p + 12, w3 * xx.x, w3 * xx.y, w3 * xx.z, w3);
    }
}

// ---------------------------------------------------------------- layer1 node finalize, tiled GEMM version:
// per 64-node tile: stage V[64][128] = elu(reconstruct) in smem (no shfl),
// then PA[64][32] = V @ W2t via register-tiled smem GEMM; attn2 dots at end.
#define TILE_N 64
#define NTILES ((NN + TILE_N - 1) / TILE_N)

// swizzled float4 index for V: (kq in 0..31, nl in 0..63)
__device__ __forceinline__ int vidx(int kq, int nl) {
    return kq * 64 + (nl ^ (((kq >> 3) & 3) << 1));
}

__global__ void k_l1n(const float* __restrict__ w1, const float* __restrict__ w2,
                      const float* __restrict__ b1,
                      const float* __restrict__ a2s, const float* __restrict__ a2d) {
    __shared__ float4 s_v4[32 * 64];    // V[k][n] as float4 over k-quads, swizzled (32KB)
    __shared__ float4 s_w2[128 * 8];    // W2t[k][cg*4..cg*4+3] (16KB)
    int tid = threadIdx.x;
    // stage W2t once per block
    for (int i = tid; i < 1024; i += 256) {
        int k = i >> 3, cg = i & 7;
        float4 wv;
        wv.x = __ldg(w2 + (cg * 4 + 0) * 128 + k);
        wv.y = __ldg(w2 + (cg * 4 + 1) * 128 + k);
        wv.z = __ldg(w2 + (cg * 4 + 2) * 128 + k);
        wv.w = __ldg(w2 + (cg * 4 + 3) * 128 + k);
        s_w2[i] = wv;
    }
    int wrp  = tid >> 5;
    int lane = tid & 31;
    int cg   = lane & 7;
    int grp  = lane >> 3;
    // stage-1 mapping
    int nl1 = tid >> 2;         // 0..63
    int hd  = tid & 3;          // head (= k block of 32)
    float4 a2sv = *(const float4*)(a2s + cg * 4);
    float4 a2dv = *(const float4*)(a2d + cg * 4);

    for (int tile = blockIdx.x; tile < NTILES; tile += gridDim.x) {
        int nbase = tile * TILE_N;
        __syncthreads();   // protect s_v4 from previous iteration's readers
        // ---- stage 1: V[nl][k] for k in head block, elementwise (no shfl)
        {
            int n = nbase + nl1;
            if (n < NN) {
                float4 A = *(const float4*)(g_acc1 + n * 16 + hd * 4);
                float inv = 1.f / (A.w + EPSV);
#pragma unroll
                for (int i = 0; i < 8; i++) {
                    int k0 = hd * 32 + i * 4;
                    float4 vv;
                    vv.x = eluf((__ldg(w1 + (k0 + 0) * 3) * A.x + __ldg(w1 + (k0 + 0) * 3 + 1) * A.y + __ldg(w1 + (k0 + 0) * 3 + 2) * A.z) * inv + __ldg(b1 + k0 + 0));
                    vv.y = eluf((__ldg(w1 + (k0 + 1) * 3) * A.x + __ldg(w1 + (k0 + 1) * 3 + 1) * A.y + __ldg(w1 + (k0 + 1) * 3 + 2) * A.z) * inv + __ldg(b1 + k0 + 1));
                    vv.z = eluf((__ldg(w1 + (k0 + 2) * 3) * A.x + __ldg(w1 + (k0 + 2) * 3 + 1) * A.y + __ldg(w1 + (k0 + 2) * 3 + 2) * A.z) * inv + __ldg(b1 + k0 + 2));
                    vv.w = eluf((__ldg(w1 + (k0 + 3) * 3) * A.x + __ldg(w1 + (k0 + 3) * 3 + 1) * A.y + __ldg(w1 + (k0 + 3) * 3 + 2) * A.z) * inv + __ldg(b1 + k0 + 3));
                    s_v4[vidx(hd * 8 + i, nl1)] = vv;
                }
            }
        }
        __syncthreads();
        // ---- stage 2: PA[64][32] = V @ W2t, thread = 2 nodes x 4 cols
        int ln0 = wrp * 8 + grp * 2;
        int ln1 = ln0 + 1;
        float4 acc0 = make_float4(0.f, 0.f, 0.f, 0.f);
        float4 acc1 = make_float4(0.f, 0.f, 0.f, 0.f);
#pragma unroll
        for (int kq = 0; kq < 32; kq++) {
            float4 v0 = s_v4[vidx(kq, ln0)];
            float4 v1 = s_v4[vidx(kq, ln1)];
            float4 wq;
            wq = s_w2[(kq * 4 + 0) * 8 + cg];
            acc0.x += v0.x * wq.x; acc0.y += v0.x * wq.y; acc0.z += v0.x * wq.z; acc0.w += v0.x * wq.w;
            acc1.x += v1.x * wq.x; acc1.y += v1.x * wq.y; acc1.z += v1.x * wq.z; acc1.w += v1.x * wq.w;
            wq = s_w2[(kq * 4 + 1) * 8 + cg];
            acc0.x += v0.y * wq.x; acc0.y += v0.y * wq.y; acc0.z += v0.y * wq.z; acc0.w += v0.y * wq.w;
            acc1.x += v1.y * wq.x; acc1.y += v1.y * wq.y; acc1.z += v1.y * wq.z; acc1.w += v1.y * wq.w;
            wq = s_w2[(kq * 4 + 2) * 8 + cg];
            acc0.x += v0.z * wq.x; acc0.y += v0.z * wq.y; acc0.z += v0.z * wq.z; acc0.w += v0.z * wq.w;
            acc1.x += v1.z * wq.x; acc1.y += v1.z * wq.y; acc1.z += v1.z * wq.z; acc1.w += v1.z * wq.w;
            wq = s_w2[(kq * 4 + 3) * 8 + cg];
            acc0.x += v0.w * wq.x; acc0.y += v0.w * wq.y; acc0.z += v0.w * wq.z; acc0.w += v0.w * wq.w;
            acc1.x += v1.w * wq.x; acc1.y += v1.w * wq.y; acc1.z += v1.w * wq.z; acc1.w += v1.w * wq.w;
        }
        // ---- writeback + attn2 dots
        int n0 = nbase + ln0, n1 = nbase + ln1;
        float ts0 = acc0.x * a2sv.x + acc0.y * a2sv.y + acc0.z * a2sv.z + acc0.w * a2sv.w;
        float td0 = acc0.x * a2dv.x + acc0.y * a2dv.y + acc0.z * a2dv.z + acc0.w * a2dv.w;
        float ts1 = acc1.x * a2sv.x + acc1.y * a2sv.y + acc1.z * a2sv.z + acc1.w * a2sv.w;
        float td1 = acc1.x * a2dv.x + acc1.y * a2dv.y + acc1.z * a2dv.z + acc1.w * a2dv.w;
#pragma unroll
        for (int o = 4; o > 0; o >>= 1) {
            ts0 += __shfl_xor_sync(0xffffffffu, ts0, o);
            td0 += __shfl_xor_sync(0xffffffffu, td0, o);
            ts1 += __shfl_xor_sync(0xffffffffu, ts1, o);
            td1 += __shfl_xor_sync(0xffffffffu, td1, o);
        }
        if (n0 < NN) {
            *(float4*)(g_h2 + n0 * 32 + cg * 4) = acc0;
            if (cg == 0) { g_as2[n0] = ts0; g_ad2[n0] = td0; }
        }
        if (n1 < NN) {
            *(float4*)(g_h2 + n1 * 32 + cg * 4) = acc1;
            if (cg == 0) { g_as2[n1] = ts1; g_ad2[n1] = td1; }
        }
    }
}

// ---------------------------------------------------------------- layer2 edge accumulation (8 lanes per edge)
__global__ void k_l2e(const int* __restrict__ src, const int* __restrict__ dst) {
    int tid = threadIdx.x;
    int lane = tid & 31;
    int sub = lane & 7;
    int warp = (blockIdx.x * blockDim.x + tid) >> 5;
    int nw = (gridDim.x * blockDim.x) >> 5;
    for (int base = warp * 4; base < NE; base += nw * 4) {
        int e = base + (lane >> 3);   // NE % 4 == 0 → always valid
        int s = src[e], d = dst[e];
        float w = __expf(lrelu(g_as2[s] + g_ad2[d]));
        float4 h = *(const float4*)(g_h2 + s * 32 + sub * 4);
        red4(g_acc2 + d * 32 + sub * 4, w * h.x, w * h.y, w * h.z, w * h.w);
        if (sub == 0) red1(g_den2 + d, w);
    }
}

// ---------------------------------------------------------------- layer2 node finalize (warp per node)
__global__ void k_l2n(const float* __restrict__ b2, const float* __restrict__ mw1,
                      const float* __restrict__ mb1) {
    __shared__ float s_wa[32 * 32];
    __shared__ float s_wb[32 * 32];
    int tid = threadIdx.x;
    for (int i = tid; i < 1024; i += blockDim.x) {
        int r = i >> 5, k = i & 31;
        s_wa[k * 32 + r] = mw1[r * 64 + k];
        s_wb[k * 32 + r] = mw1[r * 64 + 32 + k];
    }
    __syncthreads();
    int lane = tid & 31;
    int warp = (blockIdx.x * blockDim.x + tid) >> 5;
    int nw = (gridDim.x * blockDim.x) >> 5;
    for (int n = warp; n < NN; n += nw) {
        float o = g_acc2[n * 32 + lane] / (g_den2[n] + EPSV) + __ldg(b2 + lane);
        float u0 = 0.f, u1 = 0.f, v0 = 0.f, v1 = 0.f;
#pragma unroll
        for (int k = 0; k < 32; k += 2) {
            float bc0 = __shfl_sync(0xffffffffu, o, k);
            float bc1 = __shfl_sync(0xffffffffu, o, k + 1);
            u0 += s_wa[k * 32 + lane] * bc0;
            u1 += s_wa[(k + 1) * 32 + lane] * bc1;
            v0 += s_wb[k * 32 + lane] * bc0;
            v1 += s_wb[(k + 1) * 32 + lane] * bc1;
        }
        g_u[n * 32 + lane] = u0 + u1;
        g_v[n * 32 + lane] = v0 + v1 + __ldg(mb1 + lane);
    }
}

// ---------------------------------------------------------------- edge MLP: 8 lanes per edge
__global__ void k_mlp(const float* __restrict__ mw2, const float* __restrict__ mb2,
                      float* __restrict__ out,
                      const int* __restrict__ src, const int* __restrict__ dst) {
    int tid = threadIdx.x;
    int lane = tid & 31;
    int sub = lane & 7;
    int warp = (blockIdx.x * blockDim.x + tid) >> 5;
    int nw = (gridDim.x * blockDim.x) >> 5;
    float4 w2v = *(const float4*)(mw2 + sub * 4);
    float fb = __ldg(mb2);
    for (int base = warp * 4; base < NE; base += nw * 4) {
        int e = base + (lane >> 3);
        int s = src[e], d = dst[e];
        float4 uu = *(const float4*)(g_u + s * 32 + sub * 4);
        float4 vv = *(const float4*)(g_v + d * 32 + sub * 4);
        float t = fmaxf(uu.x + vv.x, 0.f) * w2v.x
                + fmaxf(uu.y + vv.y, 0.f) * w2v.y
                + fmaxf(uu.z + vv.z, 0.f) * w2v.z
                + fmaxf(uu.w + vv.w, 0.f) * w2v.w;
        t += __shfl_xor_sync(0xffffffffu, t, 4);
        t += __shfl_xor_sync(0xffffffffu, t, 2);
        t += __shfl_xor_sync(0xffffffffu, t, 1);
        if (sub == 0) out[e] = fmaxf(t + fb, 0.f);
    }
}

extern "C" void kernel_launch(void* const* d_in, const int* in_sizes, int n_in,
                              void* d_out, int out_size) {
    const float* x   = (const float*)d_in[0];
    const int*   ei  = (const int*)d_in[1];
    const float* w1  = (const float*)d_in[2];
    const float* as1 = (const float*)d_in[3];
    const float* ad1 = (const float*)d_in[4];
    const float* b1  = (const float*)d_in[5];
    const float* w2  = (const float*)d_in[6];
    const float* as2 = (const float*)d_in[7];
    const float* ad2 = (const float*)d_in[8];
    const float* b2  = (const float*)d_in[9];
    const float* mw1 = (const float*)d_in[10];
    const float* mb1 = (const float*)d_in[11];
    const float* mw2 = (const float*)d_in[12];
    const float* mb2 = (const float*)d_in[13];
    const int* src = ei;
    const int* dst = ei + NE;
    float* out = (float*)d_out;

    k_zero <<<2048, 256>>>(w1, as1, ad1);
    k_node1<<<(NN + 255) / 256, 256>>>(x);
    k_l1e  <<<2048, 256>>>(src, dst);
    k_l1n  <<<NTILES, 256>>>(w1, w2, b1, as2, ad2);
    k_l2e  <<<2048, 256>>>(src, dst);
    k_l2n  <<<512, 256>>>(b2, mw1, mb1);
    k_mlp  <<<2048, 256>>>(mw2, mb2, out, src, dst);
}

// round 13
// speedup vs baseline: 1.3643x; 1.0332x over previous
#include <cuda_runtime.h>

#define NN 100000
#define NE 1600000
#define EPSV 1e-16f
#define NEG 0.2f

// Scratch (static __device__ — allocation-free)
__device__ float    g_rec1[NN * 8];  // per node: {as1[4], x0,x1,x2,0}
__device__ float    g_ad1[NN * 4];   // ad1 per node (4 heads)
__device__ float    g_acc1[NN * 16]; // layer1 rank-3 accumulators (4 heads x {wx0,wx1,wx2,w})
__device__ float    g_h2[NN * 32];
__device__ float    g_as2[NN];
__device__ float    g_ad2[NN];
__device__ float    g_acc2[NN * 32]; // layer2 weighted-sum accumulator
__device__ float    g_den2[NN];      // layer2 softmax denominator
__device__ float    g_u[NN * 32];
__device__ float    g_v[NN * 32];
__device__ float    g_p[24];         // folded attn: p_src[4][3], p_dst[4][3]

__device__ __forceinline__ float lrelu(float x) { return x > 0.f ? x : NEG * x; }
__device__ __forceinline__ float eluf(float x)  { return x > 0.f ? x : (__expf(x) - 1.f); }

__device__ __forceinline__ void red4(float* p, float a, float b, float c, float d) {
    asm volatile("red.global.add.v4.f32 [%0], {%1,%2,%3,%4};"
                 :: "l"(p), "f"(a), "f"(b), "f"(c), "f"(d) : "memory");
}
__device__ __forceinline__ void red1(float* p, float v) {
    asm volatile("red.global.add.f32 [%0], %1;" :: "l"(p), "f"(v) : "memory");
}

// ---------------------------------------------------------------- zero accumulators + fold attn vectors into W1 (block 0)
__global__ void k_zero(const float* __restrict__ w1, const float* __restrict__ as_,
                       const float* __restrict__ ad_) {
    int i = blockIdx.x * blockDim.x + threadIdx.x;
    int st = gridDim.x * blockDim.x;
    for (int j = i; j < NN * 16; j += st) g_acc1[j] = 0.f;
    for (int j = i; j < NN * 32; j += st) g_acc2[j] = 0.f;
    for (int j = i; j < NN;      j += st) g_den2[j] = 0.f;
    if (blockIdx.x == 0 && threadIdx.x < 24) {
        int t = threadIdx.x;
        int sd = t / 12;               // 0 = src, 1 = dst
        int h  = (t % 12) / 3;
        int j  = t % 3;
        const float* a = sd ? ad_ : as_;
        float acc = 0.f;
        for (int c = 0; c < 32; c++)
            acc += a[h * 32 + c] * w1[(h * 32 + c) * 3 + j];
        g_p[sd * 12 + h * 3 + j] = acc;
    }
}

// ---------------------------------------------------------------- node1: thread per node
__global__ void k_node1(const float* __restrict__ x) {
    __shared__ float sp[24];
    if (threadIdx.x < 24) sp[threadIdx.x] = g_p[threadIdx.x];
    __syncthreads();
    int n = blockIdx.x * blockDim.x + threadIdx.x;
    if (n >= NN) return;
    float x0 = __ldg(x + n * 3);
    float x1 = __ldg(x + n * 3 + 1);
    float x2 = __ldg(x + n * 3 + 2);
    float4 as, ad;
    as.x = x0 * sp[0]  + x1 * sp[1]  + x2 * sp[2];
    as.y = x0 * sp[3]  + x1 * sp[4]  + x2 * sp[5];
    as.z = x0 * sp[6]  + x1 * sp[7]  + x2 * sp[8];
    as.w = x0 * sp[9]  + x1 * sp[10] + x2 * sp[11];
    ad.x = x0 * sp[12] + x1 * sp[13] + x2 * sp[14];
    ad.y = x0 * sp[15] + x1 * sp[16] + x2 * sp[17];
    ad.z = x0 * sp[18] + x1 * sp[19] + x2 * sp[20];
    ad.w = x0 * sp[21] + x1 * sp[22] + x2 * sp[23];
    *(float4*)(g_rec1 + n * 8)     = as;
    *(float4*)(g_rec1 + n * 8 + 4) = make_float4(x0, x1, x2, 0.f);
    *(float4*)(g_ad1 + n * 4)      = ad;
}

// ---------------------------------------------------------------- layer1 edge accumulation (thread per edge)
__global__ void k_l1e(const int* __restrict__ src, const int* __restrict__ dst) {
    int i = blockIdx.x * blockDim.x + threadIdx.x;
    int st = gridDim.x * blockDim.x;
    for (int e = i; e < NE; e += st) {
        int s = src[e], d = dst[e];
        float4 as = *(const float4*)(g_rec1 + s * 8);
        float4 xx = *(const float4*)(g_rec1 + s * 8 + 4);
        float4 ad = *(const float4*)(g_ad1 + d * 4);
        float w0 = __expf(lrelu(as.x + ad.x));
        float w1 = __expf(lrelu(as.y + ad.y));
        float w2 = __expf(lrelu(as.z + ad.z));
        float w3 = __expf(lrelu(as.w + ad.w));
        float* p = g_acc1 + d * 16;
        red4(p,      w0 * xx.x, w0 * xx.y, w0 * xx.z, w0);
        red4(p + 4,  w1 * xx.x, w1 * xx.y, w1 * xx.z, w1);
        red4(p + 8,  w2 * xx.x, w2 * xx.y, w2 * xx.z, w2);
        red4(p + 12, w3 * xx.x, w3 * xx.y, w3 * xx.z, w3);
    }
}

// ---------------------------------------------------------------- layer1 node finalize, tiled GEMM:
// stage 1 (kq-major, W1/b1 in registers): V[64][128] = elu(reconstruct) into smem
// stage 2: PA[64][32] = V @ W2t via register-tiled smem GEMM; attn2 dots at end.
#define TILE_N 64
#define NTILES ((NN + TILE_N - 1) / TILE_N)

// swizzled float4 index for V: (kq in 0..31, nl in 0..63)
__device__ __forceinline__ int vidx(int kq, int nl) {
    return kq * 64 + (nl ^ (((kq >> 3) & 3) << 1));
}

__global__ void k_l1n(const float* __restrict__ w1, const float* __restrict__ w2,
                      const float* __restrict__ b1,
                      const float* __restrict__ a2s, const float* __restrict__ a2d) {
    __shared__ float4 s_v4[32 * 64];    // V[k][n] as float4 over k-quads, swizzled (32KB)
    __shared__ float4 s_w2[128 * 8];    // W2t[k][cg*4..cg*4+3] (16KB)
    int tid = threadIdx.x;
    // stage W2t once per block
    for (int i = tid; i < 1024; i += 256) {
        int k = i >> 3, cg = i & 7;
        float4 wv;
        wv.x = __ldg(w2 + (cg * 4 + 0) * 128 + k);
        wv.y = __ldg(w2 + (cg * 4 + 1) * 128 + k);
        wv.z = __ldg(w2 + (cg * 4 + 2) * 128 + k);
        wv.w = __ldg(w2 + (cg * 4 + 3) * 128 + k);
        s_w2[i] = wv;
    }
    int wrp  = tid >> 5;
    int lane = tid & 31;
    int cg   = lane & 7;
    int grp  = lane >> 3;
    int sub  = lane & 7;
    // stage-1 fixed assignment: this thread owns k-quad kq forever
    int kq = wrp * 4 + grp;            // 0..31
    int hd = kq >> 3;                  // head for this k-quad
    // W1 rows kq*4..kq*4+3 and b1 entries in registers (loaded once)
    float w1r[4][3], b1r[4];
#pragma unroll
    for (int c = 0; c < 4; c++) {
        int k0 = kq * 4 + c;
        w1r[c][0] = __ldg(w1 + k0 * 3);
        w1r[c][1] = __ldg(w1 + k0 * 3 + 1);
        w1r[c][2] = __ldg(w1 + k0 * 3 + 2);
        b1r[c]    = __ldg(b1 + k0);
    }
    float4 a2sv = *(const float4*)(a2s + cg * 4);
    float4 a2dv = *(const float4*)(a2d + cg * 4);

    for (int tile = blockIdx.x; tile < NTILES; tile += gridDim.x) {
        int nbase = tile * TILE_N;
        __syncthreads();   // protect s_v4 from previous iteration's readers
        // ---- stage 1: this thread fills V[kq][nl] for nl = sub, sub+8, ..., sub+56
#pragma unroll
        for (int it = 0; it < 8; it++) {
            int nl = sub + it * 8;
            int n = nbase + nl;
            if (n < NN) {
                float4 A = *(const float4*)(g_acc1 + n * 16 + hd * 4);
                float inv = 1.f / (A.w + EPSV);
                float4 vv;
                vv.x = eluf((w1r[0][0] * A.x + w1r[0][1] * A.y + w1r[0][2] * A.z) * inv + b1r[0]);
                vv.y = eluf((w1r[1][0] * A.x + w1r[1][1] * A.y + w1r[1][2] * A.z) * inv + b1r[1]);
                vv.z = eluf((w1r[2][0] * A.x + w1r[2][1] * A.y + w1r[2][2] * A.z) * inv + b1r[2]);
                vv.w = eluf((w1r[3][0] * A.x + w1r[3][1] * A.y + w1r[3][2] * A.z) * inv + b1r[3]);
                s_v4[vidx(kq, nl)] = vv;
            }
        }
        __syncthreads();
        // ---- stage 2: PA[64][32] = V @ W2t, thread = 2 nodes x 4 cols
        int ln0 = wrp * 8 + grp * 2;
        int ln1 = ln0 + 1;
        float4 acc0 = make_float4(0.f, 0.f, 0.f, 0.f);
        float4 acc1 = make_float4(0.f, 0.f, 0.f, 0.f);
#pragma unroll
        for (int k2 = 0; k2 < 32; k2++) {
            float4 v0 = s_v4[vidx(k2, ln0)];
            float4 v1 = s_v4[vidx(k2, ln1)];
            float4 wq;
            wq = s_w2[(k2 * 4 + 0) * 8 + cg];
            acc0.x += v0.x * wq.x; acc0.y += v0.x * wq.y; acc0.z += v0.x * wq.z; acc0.w += v0.x * wq.w;
            acc1.x += v1.x * wq.x; acc1.y += v1.x * wq.y; acc1.z += v1.x * wq.z; acc1.w += v1.x * wq.w;
            wq = s_w2[(k2 * 4 + 1) * 8 + cg];
            acc0.x += v0.y * wq.x; acc0.y += v0.y * wq.y; acc0.z += v0.y * wq.z; acc0.w += v0.y * wq.w;
            acc1.x += v1.y * wq.x; acc1.y += v1.y * wq.y; acc1.z += v1.y * wq.z; acc1.w += v1.y * wq.w;
            wq = s_w2[(k2 * 4 + 2) * 8 + cg];
            acc0.x += v0.z * wq.x; acc0.y += v0.z * wq.y; acc0.z += v0.z * wq.z; acc0.w += v0.z * wq.w;
            acc1.x += v1.z * wq.x; acc1.y += v1.z * wq.y; acc1.z += v1.z * wq.z; acc1.w += v1.z * wq.w;
            wq = s_w2[(k2 * 4 + 3) * 8 + cg];
            acc0.x += v0.w * wq.x; acc0.y += v0.w * wq.y; acc0.z += v0.w * wq.z; acc0.w += v0.w * wq.w;
            acc1.x += v1.w * wq.x; acc1.y += v1.w * wq.y; acc1.z += v1.w * wq.z; acc1.w += v1.w * wq.w;
        }
        // ---- writeback + attn2 dots
        int n0 = nbase + ln0, n1 = nbase + ln1;
        float ts0 = acc0.x * a2sv.x + acc0.y * a2sv.y + acc0.z * a2sv.z + acc0.w * a2sv.w;
        float td0 = acc0.x * a2dv.x + acc0.y * a2dv.y + acc0.z * a2dv.z + acc0.w * a2dv.w;
        float ts1 = acc1.x * a2sv.x + acc1.y * a2sv.y + acc1.z * a2sv.z + acc1.w * a2sv.w;
        float td1 = acc1.x * a2dv.x + acc1.y * a2dv.y + acc1.z * a2dv.z + acc1.w * a2dv.w;
#pragma unroll
        for (int o = 4; o > 0; o >>= 1) {
            ts0 += __shfl_xor_sync(0xffffffffu, ts0, o);
            td0 += __shfl_xor_sync(0xffffffffu, td0, o);
            ts1 += __shfl_xor_sync(0xffffffffu, ts1, o);
            td1 += __shfl_xor_sync(0xffffffffu, td1, o);
        }
        if (n0 < NN) {
            *(float4*)(g_h2 + n0 * 32 + cg * 4) = acc0;
            if (cg == 0) { g_as2[n0] = ts0; g_ad2[n0] = td0; }
        }
        if (n1 < NN) {
            *(float4*)(g_h2 + n1 * 32 + cg * 4) = acc1;
            if (cg == 0) { g_as2[n1] = ts1; g_ad2[n1] = td1; }
        }
    }
}

// ---------------------------------------------------------------- layer2 edge accumulation (8 lanes per edge)
__global__ void k_l2e(const int* __restrict__ src, const int* __restrict__ dst) {
    int tid = threadIdx.x;
    int lane = tid & 31;
    int sub = lane & 7;
    int warp = (blockIdx.x * blockDim.x + tid) >> 5;
    int nw = (gridDim.x * blockDim.x) >> 5;
    for (int base = warp * 4; base < NE; base += nw * 4) {
        int e = base + (lane >> 3);   // NE % 4 == 0 → always valid
        int s = src[e], d = dst[e];
        float w = __expf(lrelu(g_as2[s] + g_ad2[d]));
        float4 h = *(const float4*)(g_h2 + s * 32 + sub * 4);
        red4(g_acc2 + d * 32 + sub * 4, w * h.x, w * h.y, w * h.z, w * h.w);
        if (sub == 0) red1(g_den2 + d, w);
    }
}

// ---------------------------------------------------------------- layer2 node finalize (warp per node)
__global__ void k_l2n(const float* __restrict__ b2, const float* __restrict__ mw1,
                      const float* __restrict__ mb1) {
    __shared__ float s_wa[32 * 32];
    __shared__ float s_wb[32 * 32];
    int tid = threadIdx.x;
    for (int i = tid; i < 1024; i += blockDim.x) {
        int r = i >> 5, k = i & 31;
        s_wa[k * 32 + r] = mw1[r * 64 + k];
        s_wb[k * 32 + r] = mw1[r * 64 + 32 + k];
    }
    __syncthreads();
    int lane = tid & 31;
    int warp = (blockIdx.x * blockDim.x + tid) >> 5;
    int nw = (gridDim.x * blockDim.x) >> 5;
    for (int n = warp; n < NN; n += nw) {
        float o = g_acc2[n * 32 + lane] / (g_den2[n] + EPSV) + __ldg(b2 + lane);
        float u0 = 0.f, u1 = 0.f, v0 = 0.f, v1 = 0.f;
#pragma unroll
        for (int k = 0; k < 32; k += 2) {
            float bc0 = __shfl_sync(0xffffffffu, o, k);
            float bc1 = __shfl_sync(0xffffffffu, o, k + 1);
            u0 += s_wa[k * 32 + lane] * bc0;
            u1 += s_wa[(k + 1) * 32 + lane] * bc1;
            v0 += s_wb[k * 32 + lane] * bc0;
            v1 += s_wb[(k + 1) * 32 + lane] * bc1;
        }
        g_u[n * 32 + lane] = u0 + u1;
        g_v[n * 32 + lane] = v0 + v1 + __ldg(mb1 + lane);
    }
}

// ---------------------------------------------------------------- edge MLP: 8 lanes per edge
__global__ void k_mlp(const float* __restrict__ mw2, const float* __restrict__ mb2,
                      float* __restrict__ out,
                      const int* __restrict__ src, const int* __restrict__ dst) {
    int tid = threadIdx.x;
    int lane = tid & 31;
    int sub = lane & 7;
    int warp = (blockIdx.x * blockDim.x + tid) >> 5;
    int nw = (gridDim.x * blockDim.x) >> 5;
    float4 w2v = *(const float4*)(mw2 + sub * 4);
    float fb = __ldg(mb2);
    for (int base = warp * 4; base < NE; base += nw * 4) {
        int e = base + (lane >> 3);
        int s = src[e], d = dst[e];
        float4 uu = *(const float4*)(g_u + s * 32 + sub * 4);
        float4 vv = *(const float4*)(g_v + d * 32 + sub * 4);
        float t = fmaxf(uu.x + vv.x, 0.f) * w2v.x
                + fmaxf(uu.y + vv.y, 0.f) * w2v.y
                + fmaxf(uu.z + vv.z, 0.f) * w2v.z
                + fmaxf(uu.w + vv.w, 0.f) * w2v.w;
        t += __shfl_xor_sync(0xffffffffu, t, 4);
        t += __shfl_xor_sync(0xffffffffu, t, 2);
        t += __shfl_xor_sync(0xffffffffu, t, 1);
        if (sub == 0) out[e] = fmaxf(t + fb, 0.f);
    }
}

extern "C" void kernel_launch(void* const* d_in, const int* in_sizes, int n_in,
                              void* d_out, int out_size) {
    const float* x   = (const float*)d_in[0];
    const int*   ei  = (const int*)d_in[1];
    const float* w1  = (const float*)d_in[2];
    const float* as1 = (const float*)d_in[3];
    const float* ad1 = (const float*)d_in[4];
    const float* b1  = (const float*)d_in[5];
    const float* w2  = (const float*)d_in[6];
    const float* as2 = (const float*)d_in[7];
    const float* ad2 = (const float*)d_in[8];
    const float* b2  = (const float*)d_in[9];
    const float* mw1 = (const float*)d_in[10];
    const float* mb1 = (const float*)d_in[11];
    const float* mw2 = (const float*)d_in[12];
    const float* mb2 = (const float*)d_in[13];
    const int* src = ei;
    const int* dst = ei + NE;
    float* out = (float*)d_out;

    k_zero <<<2048, 256>>>(w1, as1, ad1);
    k_node1<<<(NN + 255) / 256, 256>>>(x);
    k_l1e  <<<2048, 256>>>(src, dst);
    k_l1n  <<<NTILES, 256>>>(w1, w2, b1, as2, ad2);
    k_l2e  <<<2048, 256>>>(src, dst);
    k_l2n  <<<512, 256>>>(b2, mw1, mb1);
    k_mlp  <<<2048, 256>>>(mw2, mb2, out, src, dst);
}